// round 8
// baseline (speedup 1.0000x reference)
#include <cuda_runtime.h>

#define FULLM 0xffffffffu
typedef unsigned long long ull;

namespace {
constexpr int NOUT = 32;
constexpr int KTOT = 288;   // 3*3*32
constexpr int BTOT = 576;   // 16*6*6
constexpr int NW   = 8;     // warps per block
constexpr int NSTEPS = 18;  // 36 k per warp, 2 k per stage
constexpr float EPSF = 1e-9f;
constexpr float LOG2PI = 1.8378770664093453f;
}

struct __align__(16) Smem {
    float2 pose2[KTOT][16];      // 36 KB  pose, each scalar duplicated {p,p}
    float act[KTOT];             //  1.1 KB
    char  wbuf[2][NW][2][2048];  // 64 KB  [buf][warp][half] swizzled w slices
    float acc[NOUT][33];         // S1[16], S2[16], rsum
    float mu[NOUT][18];
    float is[NOUT][18];          // 0.5 / sigma2
    float L0[NOUT];
    float a[NOUT];
};

__device__ __forceinline__ ull pk2(float a, float b) {
    ull r; asm("mov.b64 %0,{%1,%2};" : "=l"(r) : "f"(a), "f"(b)); return r;
}
__device__ __forceinline__ void upk2(ull v, float& a, float& b) {
    asm("mov.b64 {%0,%1},%2;" : "=f"(a), "=f"(b) : "l"(v));
}
__device__ __forceinline__ ull fma2(ull a, ull b, ull c) {
    ull r; asm("fma.rn.f32x2 %0,%1,%2,%3;" : "=l"(r) : "l"(a), "l"(b), "l"(c)); return r;
}
__device__ __forceinline__ ull mul2(ull a, ull b) {
    ull r; asm("mul.rn.f32x2 %0,%1,%2;" : "=l"(r) : "l"(a), "l"(b)); return r;
}
__device__ __forceinline__ ull add2(ull a, ull b) {
    ull r; asm("add.rn.f32x2 %0,%1,%2;" : "=l"(r) : "l"(a), "l"(b)); return r;
}

__device__ __forceinline__ int sw2k(int b) {      // SW128 within a 2KB slice
    return b ^ ((b >> 3) & 0x70);
}

// Stage the two k-slices (k = warp+16*st and +8) into wbuf[buf][warp][0/1].
__device__ __forceinline__ void stage_w(Smem& s, const float* __restrict__ w,
                                        int warp, int lane, int buf, int st)
{
    #pragma unroll
    for (int half = 0; half < 2; half++) {
        const int k = warp + 16 * st + 8 * half;
        const float4* gsrc = reinterpret_cast<const float4*>(w + k * 512);
        char* dst = s.wbuf[buf][warp][half];
        #pragma unroll
        for (int j = 0; j < 4; j++) {
            int unit = j * 32 + lane;                 // 16B unit, coalesced
            unsigned sa = (unsigned)__cvta_generic_to_shared(dst + sw2k(unit * 16));
            asm volatile("cp.async.cg.shared.global [%0], [%1], 16;"
                         :: "r"(sa), "l"(gsrc + unit));
        }
    }
}

// Accumulate one input capsule k; w slice read from swizzled SMEM.
template<int PASS>
__device__ __forceinline__ void accum_k(const Smem& s, int k, const char* wk,
                                        const int wsw[4],
                                        const ull A2[8], const ull B2[8],
                                        float L0eff,
                                        ull S1[8], ull S2[8], float& rsum)
{
    // lane's w[k][o][0..15] as 4x LDS.128 (conflict-free via swizzle)
    ull wpk[4][2];
    #pragma unroll
    for (int q = 0; q < 4; q++) {
        float4 f = *reinterpret_cast<const float4*>(wk + wsw[q]);
        wpk[q][0] = pk2(f.x, f.y);
        wpk[q][1] = pk2(f.z, f.w);
    }

    // vote v[m*4+n] = sum_c pose[m*4+c] * w[c*4+n]; pose pairs come
    // pre-duplicated from SMEM straight into 64-bit register pairs (no MOVs)
    ull v2[8];
    #pragma unroll
    for (int m = 0; m < 4; m++) {
        const ull* pr = reinterpret_cast<const ull*>(&s.pose2[k][m * 4]);
        ull p0 = pr[0], p1 = pr[1], p2 = pr[2], p3 = pr[3];
        #pragma unroll
        for (int h = 0; h < 2; h++) {
            ull t = mul2(p3, wpk[3][h]);
            t = fma2(p2, wpk[2][h], t);
            t = fma2(p1, wpk[1][h], t);
            v2[m * 2 + h] = fma2(p0, wpk[0][h], t);
        }
    }

    float rw;
    if (PASS == 0) {
        rw = s.act[k] * (1.f / 32.f);
    } else {
        ull acc2 = 0ull;
        #pragma unroll
        for (int i = 0; i < 8; i++) {
            ull t = fma2(A2[i], v2[i], B2[i]);   // A*v + B
            acc2 = fma2(t, v2[i], acc2);          // (A*v+B)*v
        }
        float lo, hi; upk2(acc2, lo, hi);
        float logit = L0eff - (lo + hi);
        float mx = logit;
        #pragma unroll
        for (int off = 16; off > 0; off >>= 1)
            mx = fmaxf(mx, __shfl_xor_sync(FULLM, mx, off));
        float e = __expf(logit - mx);
        float ssum = e;
        #pragma unroll
        for (int off = 16; off > 0; off >>= 1)
            ssum += __shfl_xor_sync(FULLM, ssum, off);
        rw = (e / ssum) * s.act[k];
    }

    rsum += rw;
    ull rw2 = pk2(rw, rw);
    #pragma unroll
    for (int i = 0; i < 8; i++) {
        ull t = mul2(rw2, v2[i]);
        S1[i] = add2(S1[i], t);
        S2[i] = fma2(t, v2[i], S2[i]);
    }
}

template<int PASS>
__device__ __forceinline__ void do_pass(Smem& s, const float* __restrict__ w,
                                        int tid, float inv_temp,
                                        float bv, float ba)
{
    const int warp = tid >> 5;
    const int o = tid & 31;

    for (int idx = tid; idx < NOUT * 33; idx += 256)
        (&s.acc[0][0])[idx] = 0.f;
    __syncthreads();

    // swizzled w offsets for this lane (constant across k)
    int wsw[4];
    #pragma unroll
    for (int q = 0; q < 4; q++) wsw[q] = sw2k((o * 4 + q) * 16);

    // E-step coefficients: A = 0.5/s2, B = -mu/s2, C folded into L0eff
    ull A2[8], B2[8];
    float L0eff = 0.f;
    if (PASS > 0) {
        float C = 0.f;
        #pragma unroll
        for (int i = 0; i < 8; i++) {
            float m0 = s.mu[o][2 * i], m1 = s.mu[o][2 * i + 1];
            float i0 = s.is[o][2 * i], i1 = s.is[o][2 * i + 1];
            A2[i] = pk2(i0, i1);
            B2[i] = pk2(-2.f * i0 * m0, -2.f * i1 * m1);
            C += i0 * m0 * m0 + i1 * m1 * m1;
        }
        L0eff = s.L0[o] - C;
    }

    ull S1[8], S2[8];
    #pragma unroll
    for (int i = 0; i < 8; i++) { S1[i] = 0ull; S2[i] = 0ull; }
    float rsum = 0.f;

    // per-warp double-buffered cp.async pipeline over the k stream
    stage_w(s, w, warp, o, 0, 0);
    asm volatile("cp.async.commit_group;");
    for (int st = 0; st < NSTEPS; st++) {
        if (st + 1 < NSTEPS)
            stage_w(s, w, warp, o, (st + 1) & 1, st + 1);
        asm volatile("cp.async.commit_group;");
        asm volatile("cp.async.wait_group 1;");
        __syncwarp();
        const int kbase = warp + 16 * st;
        accum_k<PASS>(s, kbase,     s.wbuf[st & 1][warp][0], wsw, A2, B2, L0eff, S1, S2, rsum);
        accum_k<PASS>(s, kbase + 8, s.wbuf[st & 1][warp][1], wsw, A2, B2, L0eff, S1, S2, rsum);
    }

    // cross-warp reduction (stride 33: odd -> conflict-free)
    #pragma unroll
    for (int i = 0; i < 8; i++) {
        float x, y;
        upk2(S1[i], x, y);
        atomicAdd(&s.acc[o][2 * i], x);
        atomicAdd(&s.acc[o][2 * i + 1], y);
        upk2(S2[i], x, y);
        atomicAdd(&s.acc[o][16 + 2 * i], x);
        atomicAdd(&s.acc[o][17 + 2 * i], y);
    }
    atomicAdd(&s.acc[o][32], rsum);
    __syncthreads();

    // M-step epilogue: warp 0, lane = o
    if (tid < 32) {
        float rs = s.acc[o][32] + EPSF;
        float irs = 1.f / rs;
        float logsum = 0.f;
        #pragma unroll
        for (int d = 0; d < 16; d++) {
            float mu = s.acc[o][d] * irs;
            float sg = fmaxf(s.acc[o][16 + d] * irs - mu * mu, 0.f) + EPSF;
            s.mu[o][d] = mu;
            s.is[o][d] = 0.5f / sg;
            logsum += __logf(sg);
        }
        float costsum = (16.f * bv + 0.5f * logsum) * rs;
        float x = inv_temp * (ba - costsum);
        float a = 1.f / (1.f + __expf(-x));
        s.a[o] = a;
        s.L0[o] = __logf(a + EPSF) - 0.5f * (16.f * LOG2PI + logsum);
    }
    __syncthreads();
}

__global__ void __launch_bounds__(256, 2)
convcaps_kernel(const float* __restrict__ pose,
                const float* __restrict__ act,
                const float* __restrict__ w,
                const float* __restrict__ beta_v,
                const float* __restrict__ beta_a,
                float* __restrict__ out)
{
    extern __shared__ char smem_raw[];
    Smem& s = *reinterpret_cast<Smem*>(smem_raw);
    const int b = blockIdx.x;
    const int n = b / 36, rem = b % 36;
    const int h0 = (rem / 6) * 2, w0c = (rem % 6) * 2;
    const int tid = threadIdx.x;

    // im2col load of the 3x3x32 capsule neighborhood; pose written duplicated
    for (int idx = tid; idx < KTOT * 4; idx += 256) {
        int k = idx >> 2, q = idx & 3;
        int ki = k / 96, kj = (k >> 5) % 3, c = k & 31;
        float4 v = *(reinterpret_cast<const float4*>(
            pose + ((((n * 14 + h0 + ki) * 14) + (w0c + kj)) * 32 + c) * 16) + q);
        s.pose2[k][q * 4 + 0] = make_float2(v.x, v.x);
        s.pose2[k][q * 4 + 1] = make_float2(v.y, v.y);
        s.pose2[k][q * 4 + 2] = make_float2(v.z, v.z);
        s.pose2[k][q * 4 + 3] = make_float2(v.w, v.w);
    }
    for (int k = tid; k < KTOT; k += 256) {
        int ki = k / 96, kj = (k >> 5) % 3, c = k & 31;
        s.act[k] = act[((n * 14 + h0 + ki) * 14 + (w0c + kj)) * 32 + c];
    }

    const int o = tid & 31;
    const float bv = beta_v[o];
    const float ba = beta_a[o];

    // 3 fused passes: M0, E0+M1, E1+M2  (inv_temp = 0.01*(1-0.95^(it+1)))
    do_pass<0>(s, w, tid, 0.0005f,     bv, ba);
    do_pass<1>(s, w, tid, 0.000975f,   bv, ba);
    do_pass<2>(s, w, tid, 0.00142625f, bv, ba);

    // outputs: pose (B,O,16) then activation (B,O)
    for (int idx = tid; idx < NOUT * 16; idx += 256)
        out[b * 512 + idx] = s.mu[idx >> 4][idx & 15];
    if (tid < 32)
        out[BTOT * 512 + b * 32 + tid] = s.a[tid];
}

extern "C" void kernel_launch(void* const* d_in, const int* in_sizes, int n_in,
                              void* d_out, int out_size) {
    const float* pose = (const float*)d_in[0];
    const float* act  = (const float*)d_in[1];
    const float* w    = (const float*)d_in[2];
    const float* bv   = (const float*)d_in[3];
    const float* ba   = (const float*)d_in[4];
    cudaFuncSetAttribute(convcaps_kernel,
                         cudaFuncAttributeMaxDynamicSharedMemorySize,
                         (int)sizeof(Smem));
    convcaps_kernel<<<BTOT, 256, sizeof(Smem)>>>(pose, act, w, bv, ba,
                                                 (float*)d_out);
}

// round 9
// speedup vs baseline: 1.0941x; 1.0941x over previous
#include <cuda_runtime.h>

#define FULLM 0xffffffffu
typedef unsigned long long ull;

namespace {
constexpr int NOUT = 32;
constexpr int KTOT = 288;   // 3*3*32
constexpr int BTOT = 576;   // 16*6*6
constexpr int NW   = 8;     // warps per block
constexpr int NSTEPS = 18;  // 36 k per warp, 2 k per stage
constexpr float EPSF = 1e-9f;
constexpr float LOG2PI = 1.8378770664093453f;
constexpr float LOG2E  = 1.4426950408889634f;
}

struct __align__(16) Smem {
    float pose[KTOT][16];        // 18 KB  im2col'd pose tile
    float act[KTOT];             //  1.1 KB
    char  wbuf[2][NW][2][2048];  // 64 KB  [buf][warp][half] swizzled w slices
    float acc[NOUT][33];         // S1[16], S2[16], rsum
    float mu[NOUT][18];
    float is[NOUT][18];          // 0.5 / sigma2
    float L0[NOUT];
    float a[NOUT];
};

__device__ __forceinline__ ull pk2(float a, float b) {
    ull r; asm("mov.b64 %0,{%1,%2};" : "=l"(r) : "f"(a), "f"(b)); return r;
}
__device__ __forceinline__ void upk2(ull v, float& a, float& b) {
    asm("mov.b64 {%0,%1},%2;" : "=f"(a), "=f"(b) : "l"(v));
}
__device__ __forceinline__ ull fma2(ull a, ull b, ull c) {
    ull r; asm("fma.rn.f32x2 %0,%1,%2,%3;" : "=l"(r) : "l"(a), "l"(b), "l"(c)); return r;
}
__device__ __forceinline__ ull mul2(ull a, ull b) {
    ull r; asm("mul.rn.f32x2 %0,%1,%2;" : "=l"(r) : "l"(a), "l"(b)); return r;
}
__device__ __forceinline__ ull add2(ull a, ull b) {
    ull r; asm("add.rn.f32x2 %0,%1,%2;" : "=l"(r) : "l"(a), "l"(b)); return r;
}

__device__ __forceinline__ int sw2k(int b) {      // SW128 within a 2KB slice
    return b ^ ((b >> 3) & 0x70);
}

// Stage the two k-slices (k = warp+16*st and +8) into wbuf[buf][warp][0/1].
__device__ __forceinline__ void stage_w(Smem& s, const float* __restrict__ w,
                                        int warp, int lane, int buf, int st)
{
    #pragma unroll
    for (int half = 0; half < 2; half++) {
        const int k = warp + 16 * st + 8 * half;
        const float4* gsrc = reinterpret_cast<const float4*>(w + k * 512);
        char* dst = s.wbuf[buf][warp][half];
        #pragma unroll
        for (int j = 0; j < 4; j++) {
            int unit = j * 32 + lane;                 // 16B unit, coalesced
            unsigned sa = (unsigned)__cvta_generic_to_shared(dst + sw2k(unit * 16));
            asm volatile("cp.async.cg.shared.global [%0], [%1], 16;"
                         :: "r"(sa), "l"(gsrc + unit));
        }
    }
}

// Compute votes for capsule k from swizzled SMEM w-slice.
__device__ __forceinline__ void votes_k(const Smem& s, int k, const char* wk,
                                        const int wsw[4], ull v2[8])
{
    ull wpk[4][2];
    #pragma unroll
    for (int q = 0; q < 4; q++) {
        float4 f = *reinterpret_cast<const float4*>(wk + wsw[q]);
        wpk[q][0] = pk2(f.x, f.y);
        wpk[q][1] = pk2(f.z, f.w);
    }
    #pragma unroll
    for (int m = 0; m < 4; m++) {
        float4 pr = *(const float4*)&s.pose[k][m * 4];
        ull p0 = pk2(pr.x, pr.x), p1 = pk2(pr.y, pr.y);
        ull p2 = pk2(pr.z, pr.z), p3 = pk2(pr.w, pr.w);
        #pragma unroll
        for (int h = 0; h < 2; h++) {
            ull t = mul2(p3, wpk[3][h]);
            t = fma2(p2, wpk[2][h], t);
            t = fma2(p1, wpk[1][h], t);
            v2[m * 2 + h] = fma2(p0, wpk[0][h], t);
        }
    }
}

// logit (base-2) = L0eff - sum_d (A*v + B)*v, two 4-deep chains for ILP
__device__ __forceinline__ float logit2_of(const ull v2[8], const ull A2[8],
                                           const ull B2[8], float L0eff)
{
    ull lo = 0ull, hi = 0ull;
    #pragma unroll
    for (int i = 0; i < 4; i++) {
        ull ta = fma2(A2[i], v2[i], B2[i]);
        lo = fma2(ta, v2[i], lo);
        ull tb = fma2(A2[4 + i], v2[4 + i], B2[4 + i]);
        hi = fma2(tb, v2[4 + i], hi);
    }
    ull t = add2(lo, hi);
    float x, y; upk2(t, x, y);
    return L0eff - (x + y);
}

// Process one stage: the two k's (k0 = kbase, k1 = kbase+8) with interleaved
// softmax reductions so the two shfl chains hide each other's latency.
template<int PASS>
__device__ __forceinline__ void accum_stage(const Smem& s, int k0, int k1,
                                            const char* wk0, const char* wk1,
                                            const int wsw[4],
                                            const ull A2[8], const ull B2[8],
                                            float L0eff,
                                            ull S1[8], ull S2[8], float& rsum)
{
    ull v2a[8], v2b[8];
    votes_k(s, k0, wk0, wsw, v2a);
    votes_k(s, k1, wk1, wsw, v2b);

    float rwA, rwB;
    if (PASS == 0) {
        rwA = s.act[k0] * (1.f / 32.f);
        rwB = s.act[k1] * (1.f / 32.f);
    } else {
        float la = logit2_of(v2a, A2, B2, L0eff);
        float lb = logit2_of(v2b, A2, B2, L0eff);
        float mxa = la, mxb = lb;
        #pragma unroll
        for (int off = 16; off > 0; off >>= 1) {
            float ta = __shfl_xor_sync(FULLM, mxa, off);
            float tb = __shfl_xor_sync(FULLM, mxb, off);
            mxa = fmaxf(mxa, ta);
            mxb = fmaxf(mxb, tb);
        }
        float ea = exp2f(la - mxa);
        float eb = exp2f(lb - mxb);
        float sa = ea, sb = eb;
        #pragma unroll
        for (int off = 16; off > 0; off >>= 1) {
            float ta = __shfl_xor_sync(FULLM, sa, off);
            float tb = __shfl_xor_sync(FULLM, sb, off);
            sa += ta;
            sb += tb;
        }
        rwA = __fdividef(ea, sa) * s.act[k0];
        rwB = __fdividef(eb, sb) * s.act[k1];
    }

    rsum += rwA + rwB;
    ull rwA2 = pk2(rwA, rwA), rwB2 = pk2(rwB, rwB);
    #pragma unroll
    for (int i = 0; i < 8; i++) {
        ull ta = mul2(rwA2, v2a[i]);
        ull tb = mul2(rwB2, v2b[i]);
        S1[i] = add2(add2(S1[i], ta), tb);
        S2[i] = fma2(tb, v2b[i], fma2(ta, v2a[i], S2[i]));
    }
}

template<int PASS>
__device__ __forceinline__ void do_pass(Smem& s, const float* __restrict__ w,
                                        int tid, float inv_temp,
                                        float bv, float ba)
{
    const int warp = tid >> 5;
    const int o = tid & 31;

    for (int idx = tid; idx < NOUT * 33; idx += 256)
        (&s.acc[0][0])[idx] = 0.f;
    __syncthreads();

    // swizzled w offsets for this lane (constant across k)
    int wsw[4];
    #pragma unroll
    for (int q = 0; q < 4; q++) wsw[q] = sw2k((o * 4 + q) * 16);

    // E-step coefficients pre-scaled to base-2: A=0.5*log2e/s2, B=-mu*log2e/s2
    ull A2[8], B2[8];
    float L0eff = 0.f;
    if (PASS > 0) {
        float C = 0.f;
        #pragma unroll
        for (int i = 0; i < 8; i++) {
            float m0 = s.mu[o][2 * i], m1 = s.mu[o][2 * i + 1];
            float i0 = s.is[o][2 * i] * LOG2E, i1 = s.is[o][2 * i + 1] * LOG2E;
            A2[i] = pk2(i0, i1);
            B2[i] = pk2(-2.f * i0 * m0, -2.f * i1 * m1);
            C += i0 * m0 * m0 + i1 * m1 * m1;
        }
        L0eff = s.L0[o] * LOG2E - C;
    }

    ull S1[8], S2[8];
    #pragma unroll
    for (int i = 0; i < 8; i++) { S1[i] = 0ull; S2[i] = 0ull; }
    float rsum = 0.f;

    // per-warp double-buffered cp.async pipeline over the k stream
    stage_w(s, w, warp, o, 0, 0);
    asm volatile("cp.async.commit_group;");
    for (int st = 0; st < NSTEPS; st++) {
        if (st + 1 < NSTEPS)
            stage_w(s, w, warp, o, (st + 1) & 1, st + 1);
        asm volatile("cp.async.commit_group;");
        asm volatile("cp.async.wait_group 1;");
        __syncwarp();
        const int kbase = warp + 16 * st;
        accum_stage<PASS>(s, kbase, kbase + 8,
                          s.wbuf[st & 1][warp][0], s.wbuf[st & 1][warp][1],
                          wsw, A2, B2, L0eff, S1, S2, rsum);
    }

    // cross-warp reduction (stride 33: odd -> conflict-free)
    #pragma unroll
    for (int i = 0; i < 8; i++) {
        float x, y;
        upk2(S1[i], x, y);
        atomicAdd(&s.acc[o][2 * i], x);
        atomicAdd(&s.acc[o][2 * i + 1], y);
        upk2(S2[i], x, y);
        atomicAdd(&s.acc[o][16 + 2 * i], x);
        atomicAdd(&s.acc[o][17 + 2 * i], y);
    }
    atomicAdd(&s.acc[o][32], rsum);
    __syncthreads();

    // M-step epilogue: warp 0, lane = o
    if (tid < 32) {
        float rs = s.acc[o][32] + EPSF;
        float irs = 1.f / rs;
        float logsum = 0.f;
        #pragma unroll
        for (int d = 0; d < 16; d++) {
            float mu = s.acc[o][d] * irs;
            float sg = fmaxf(s.acc[o][16 + d] * irs - mu * mu, 0.f) + EPSF;
            s.mu[o][d] = mu;
            s.is[o][d] = 0.5f / sg;
            logsum += __logf(sg);
        }
        float costsum = (16.f * bv + 0.5f * logsum) * rs;
        float x = inv_temp * (ba - costsum);
        float a = 1.f / (1.f + __expf(-x));
        s.a[o] = a;
        s.L0[o] = __logf(a + EPSF) - 0.5f * (16.f * LOG2PI + logsum);
    }
    __syncthreads();
}

__global__ void __launch_bounds__(256, 2)
convcaps_kernel(const float* __restrict__ pose,
                const float* __restrict__ act,
                const float* __restrict__ w,
                const float* __restrict__ beta_v,
                const float* __restrict__ beta_a,
                float* __restrict__ out)
{
    extern __shared__ char smem_raw[];
    Smem& s = *reinterpret_cast<Smem*>(smem_raw);
    const int b = blockIdx.x;
    const int n = b / 36, rem = b % 36;
    const int h0 = (rem / 6) * 2, w0c = (rem % 6) * 2;
    const int tid = threadIdx.x;

    // im2col load of the 3x3x32 capsule neighborhood (poses float4 + acts)
    for (int idx = tid; idx < KTOT * 4; idx += 256) {
        int k = idx >> 2, q = idx & 3;
        int ki = k / 96, kj = (k >> 5) % 3, c = k & 31;
        const float4* src = reinterpret_cast<const float4*>(
            pose + ((((n * 14 + h0 + ki) * 14) + (w0c + kj)) * 32 + c) * 16) + q;
        *reinterpret_cast<float4*>(&s.pose[k][q * 4]) = *src;
    }
    for (int k = tid; k < KTOT; k += 256) {
        int ki = k / 96, kj = (k >> 5) % 3, c = k & 31;
        s.act[k] = act[((n * 14 + h0 + ki) * 14 + (w0c + kj)) * 32 + c];
    }

    const int o = tid & 31;
    const float bv = beta_v[o];
    const float ba = beta_a[o];

    // 3 fused passes: M0, E0+M1, E1+M2  (inv_temp = 0.01*(1-0.95^(it+1)))
    do_pass<0>(s, w, tid, 0.0005f,     bv, ba);
    do_pass<1>(s, w, tid, 0.000975f,   bv, ba);
    do_pass<2>(s, w, tid, 0.00142625f, bv, ba);

    // outputs: pose (B,O,16) then activation (B,O)
    for (int idx = tid; idx < NOUT * 16; idx += 256)
        out[b * 512 + idx] = s.mu[idx >> 4][idx & 15];
    if (tid < 32)
        out[BTOT * 512 + b * 32 + tid] = s.a[tid];
}

extern "C" void kernel_launch(void* const* d_in, const int* in_sizes, int n_in,
                              void* d_out, int out_size) {
    const float* pose = (const float*)d_in[0];
    const float* act  = (const float*)d_in[1];
    const float* w    = (const float*)d_in[2];
    const float* bv   = (const float*)d_in[3];
    const float* ba   = (const float*)d_in[4];
    cudaFuncSetAttribute(convcaps_kernel,
                         cudaFuncAttributeMaxDynamicSharedMemorySize,
                         (int)sizeof(Smem));
    convcaps_kernel<<<BTOT, 256, sizeof(Smem)>>>(pose, act, w, bv, ba,
                                                 (float*)d_out);
}